// round 2
// baseline (speedup 1.0000x reference)
#include <cuda_runtime.h>
#include <cstdint>

// Reference = patchify followed by its exact inverse depatchify == identity.
// Fastest correct kernel = saturating HBM copy of 256 MiB.
//
// 64 * 1 * 1024 * 1024 floats = 67,108,864 floats = 16,777,216 float4.
// Each thread copies 4 float4 (64 bytes), batched up front for MLP=4.
// Threads: 16,777,216 / 4 = 4,194,304 -> 16384 blocks x 256 threads (exact cover).

__global__ __launch_bounds__(256) void identity_copy_kernel(
    const float4* __restrict__ src, float4* __restrict__ dst)
{
    // Each thread handles 4 consecutive-by-stride float4s.
    // Use block-contiguous layout: block b covers [b*1024, (b+1)*1024) float4s,
    // thread t reads t, t+256, t+512, t+768 within that window (coalesced per access).
    size_t base = (size_t)blockIdx.x * 1024 + threadIdx.x;

    // Front-batch loads (MLP=4), then stores.
    float4 v0 = src[base + 0 * 256];
    float4 v1 = src[base + 1 * 256];
    float4 v2 = src[base + 2 * 256];
    float4 v3 = src[base + 3 * 256];

    dst[base + 0 * 256] = v0;
    dst[base + 1 * 256] = v1;
    dst[base + 2 * 256] = v2;
    dst[base + 3 * 256] = v3;
}

extern "C" void kernel_launch(void* const* d_in, const int* in_sizes, int n_in,
                              void* d_out, int out_size)
{
    const float4* src = (const float4*)d_in[0];
    float4* dst = (float4*)d_out;

    // 67,108,864 floats -> 16,777,216 float4 -> 4,194,304 threads -> 16384 blocks.
    // (Shapes are fixed by the problem; out_size == 67108864.)
    identity_copy_kernel<<<16384, 256>>>(src, dst);
}